// round 5
// baseline (speedup 1.0000x reference)
#include <cuda_runtime.h>
#include <math.h>
#include <stdint.h>

#define D_MODEL 1024
#define N_TOK   8192
#define FF_DIM  4096
#define N_HEAD  16
#define HEAD_D  64

__device__ float g_h  [N_TOK * D_MODEL];
__device__ float g_qkv[N_TOK * 3 * D_MODEL];
__device__ float g_ctx[N_TOK * D_MODEL];
__device__ float g_x2 [N_TOK * D_MODEL];
__device__ float g_ff [N_TOK * FF_DIM];
__device__ float g_wq[3 * D_MODEL * D_MODEL];
__device__ float g_wp[D_MODEL * D_MODEL];
__device__ float g_w1[FF_DIM * D_MODEL];
__device__ float g_w2[D_MODEL * FF_DIM];

// ---------------- helpers ----------------
__device__ __forceinline__ float gelu_exact(float v) {
    return 0.5f * v * (1.0f + erff(v * 0.70710678118654752440f));
}
__device__ __forceinline__ float tf32r(float x) {
    uint32_t u;
    asm("cvt.rna.tf32.f32 %0, %1;" : "=r"(u) : "f"(x));
    return __uint_as_float(u);
}
__device__ __forceinline__ float4 tf32r4(float4 v) {
    v.x = tf32r(v.x); v.y = tf32r(v.y); v.z = tf32r(v.z); v.w = tf32r(v.w);
    return v;
}
__device__ __forceinline__ void mma_tf32(float d[4], uint32_t a0, uint32_t a1,
                                         uint32_t a2, uint32_t a3,
                                         uint32_t b0, uint32_t b1) {
    asm volatile(
        "mma.sync.aligned.m16n8k8.row.col.f32.tf32.tf32.f32 "
        "{%0,%1,%2,%3}, {%4,%5,%6,%7}, {%8,%9}, {%0,%1,%2,%3};\n"
        : "+f"(d[0]), "+f"(d[1]), "+f"(d[2]), "+f"(d[3])
        : "r"(a0), "r"(a1), "r"(a2), "r"(a3), "r"(b0), "r"(b1));
}
__device__ __forceinline__ void ldsm4(uint32_t& r0, uint32_t& r1, uint32_t& r2,
                                      uint32_t& r3, uint32_t addr) {
    asm volatile("ldmatrix.sync.aligned.m8n8.x4.shared.b16 {%0,%1,%2,%3}, [%4];"
                 : "=r"(r0), "=r"(r1), "=r"(r2), "=r"(r3) : "r"(addr));
}
__device__ __forceinline__ void cp16(uint32_t smem, const void* g) {
    asm volatile("cp.async.cg.shared.global [%0], [%1], 16;" :: "r"(smem), "l"(g));
}
__device__ __forceinline__ void cp_commit() {
    asm volatile("cp.async.commit_group;");
}
__device__ __forceinline__ void cp_wait2() {
    asm volatile("cp.async.wait_group 2;");
}

// ---------------- weight pre-round ----------------
__global__ void __launch_bounds__(256) round_w(const float* __restrict__ in,
                                               float* __restrict__ out, int n4) {
    int i = blockIdx.x * 256 + threadIdx.x;
    if (i < n4) ((float4*)out)[i] = tf32r4(((const float4*)in)[i]);
}

// ---------------- LayerNorm (tf32-rounded output) ----------------
__global__ void __launch_bounds__(256) ln_kernel(const float* __restrict__ x,
                                                 const float* __restrict__ g,
                                                 const float* __restrict__ b,
                                                 float* __restrict__ out) {
    int row = blockIdx.x;
    int t = threadIdx.x;
    const float* xr = x + (size_t)row * D_MODEL;
    float4 xv = ((const float4*)xr)[t];

    float s  = xv.x + xv.y + xv.z + xv.w;
    float sq = xv.x*xv.x + xv.y*xv.y + xv.z*xv.z + xv.w*xv.w;
    #pragma unroll
    for (int o = 16; o > 0; o >>= 1) {
        s  += __shfl_xor_sync(0xffffffffu, s,  o);
        sq += __shfl_xor_sync(0xffffffffu, sq, o);
    }
    __shared__ float red[2][8];
    int wid = t >> 5, lane = t & 31;
    if (lane == 0) { red[0][wid] = s; red[1][wid] = sq; }
    __syncthreads();
    float tot = 0.f, tot2 = 0.f;
    #pragma unroll
    for (int w = 0; w < 8; ++w) { tot += red[0][w]; tot2 += red[1][w]; }
    float mu = tot * (1.0f / D_MODEL);
    float var = tot2 * (1.0f / D_MODEL) - mu * mu;
    float rstd = rsqrtf(var + 1e-6f);

    float4 gv = ((const float4*)g)[t];
    float4 bv = ((const float4*)b)[t];
    float4 ov;
    ov.x = (xv.x - mu) * rstd * gv.x + bv.x;
    ov.y = (xv.y - mu) * rstd * gv.y + bv.y;
    ov.z = (xv.z - mu) * rstd * gv.z + bv.z;
    ov.w = (xv.w - mu) * rstd * gv.w + bv.w;
    ((float4*)(out + (size_t)row * D_MODEL))[t] = tf32r4(ov);
}

// ---------------- TF32 GEMM: 64x64 warp tiles, cp.async 4-stage + ldmatrix ----
#define BM 128
#define BN 128
#define BK 16
#define SPITCH 20
#define STAGES 4
#define STAGE_FLOATS (2 * BM * SPITCH)
#define STAGE_BYTES  (STAGE_FLOATS * 4)          // 20480
#define B_OFF_BYTES  (BM * SPITCH * 4)           // 10240

template<int EPI, int RND>
__global__ void __launch_bounds__(128) gemm_cp(const float* __restrict__ A,
                                               const float* __restrict__ Bw,
                                               const float* __restrict__ bias,
                                               const float* __restrict__ res,
                                               float* __restrict__ C,
                                               int M, int N, int K) {
    extern __shared__ float smem[];
    uint32_t smem_u = (uint32_t)__cvta_generic_to_shared(smem);

    int tid = threadIdx.x;
    int m0 = blockIdx.y * BM;
    int n0 = blockIdx.x * BN;
    int warp = tid >> 5, lane = tid & 31;
    int wm = (warp & 1) * 64;
    int wn = (warp >> 1) * 64;
    int r4 = lane >> 2, cc = lane & 3;

    float acc[4][8][4];
    #pragma unroll
    for (int i = 0; i < 4; ++i)
        #pragma unroll
        for (int j = 0; j < 8; ++j)
            #pragma unroll
            for (int k = 0; k < 4; ++k) acc[i][j][k] = 0.f;

    // loader: 128 threads, each does 4 A rows + 4 B rows (stride 32)
    int ldRow = tid >> 2;              // 0..31
    int ldQ   = (tid & 3) * 4;
    const float* Ap = A  + (size_t)(m0 + ldRow) * K + ldQ;
    const float* Bp = Bw + (size_t)(n0 + ldRow) * K + ldQ;
    size_t quart = (size_t)32 * K;
    uint32_t soff[4];
    #pragma unroll
    for (int i = 0; i < 4; ++i)
        soff[i] = ((ldRow + 32 * i) * SPITCH + ldQ) * 4;

    // ldmatrix lane addressing
    int aRow = wm + (lane & 15);
    int aColB = ((lane >> 4) << 2);
    uint32_t aBase = smem_u + (uint32_t)((aRow * SPITCH + aColB) * 4);
    int bRow = wn + (lane & 7) + ((lane & 16) >> 1);
    int bColB = ((lane & 8) >> 1);
    uint32_t bBase = smem_u + B_OFF_BYTES + (uint32_t)((bRow * SPITCH + bColB) * 4);

    int ntiles = K / BK;

    #pragma unroll
    for (int s = 0; s < STAGES - 1; ++s) {
        uint32_t sb = smem_u + s * STAGE_BYTES;
        int off = s * BK;
        #pragma unroll
        for (int i = 0; i < 4; ++i) {
            cp16(sb + soff[i], Ap + quart * i + off);
            cp16(sb + B_OFF_BYTES + soff[i], Bp + quart * i + off);
        }
        cp_commit();
    }

    for (int t = 0; t < ntiles; ++t) {
        cp_wait2();
        __syncthreads();

        int tp = t + STAGES - 1;
        if (tp < ntiles) {
            uint32_t sb = smem_u + (tp & (STAGES - 1)) * STAGE_BYTES;
            int off = tp * BK;
            #pragma unroll
            for (int i = 0; i < 4; ++i) {
                cp16(sb + soff[i], Ap + quart * i + off);
                cp16(sb + B_OFF_BYTES + soff[i], Bp + quart * i + off);
            }
        }
        cp_commit();

        uint32_t stg = (t & (STAGES - 1)) * STAGE_BYTES;
        #pragma unroll
        for (int ks = 0; ks < 2; ++ks) {
            uint32_t kof = stg + ks * 32;
            uint32_t af[4][4], bf[8][2];
            #pragma unroll
            for (int mt = 0; mt < 4; ++mt)
                ldsm4(af[mt][0], af[mt][1], af[mt][2], af[mt][3],
                      aBase + kof + mt * (16 * SPITCH * 4));
            #pragma unroll
            for (int np = 0; np < 4; ++np)
                ldsm4(bf[2*np][0], bf[2*np][1], bf[2*np+1][0], bf[2*np+1][1],
                      bBase + kof + np * (16 * SPITCH * 4));
            #pragma unroll
            for (int mt = 0; mt < 4; ++mt)
                #pragma unroll
                for (int nt = 0; nt < 8; ++nt)
                    mma_tf32(acc[mt][nt], af[mt][0], af[mt][1], af[mt][2], af[mt][3],
                             bf[nt][0], bf[nt][1]);
        }
    }

    #pragma unroll
    for (int mt = 0; mt < 4; ++mt) {
        int row0 = m0 + wm + mt * 16 + r4;
        #pragma unroll
        for (int nt = 0; nt < 8; ++nt) {
            int col = n0 + wn + nt * 8 + cc * 2;
            float b0v = bias[col], b1v = bias[col + 1];
            float v0 = acc[mt][nt][0] + b0v;
            float v1 = acc[mt][nt][1] + b1v;
            float v2 = acc[mt][nt][2] + b0v;
            float v3 = acc[mt][nt][3] + b1v;
            if (EPI == 1) {
                v0 = gelu_exact(v0); v1 = gelu_exact(v1);
                v2 = gelu_exact(v2); v3 = gelu_exact(v3);
            }
            if (EPI == 2) {
                float2 r0 = *(const float2*)&res[(size_t)row0 * N + col];
                float2 r1 = *(const float2*)&res[(size_t)(row0 + 8) * N + col];
                v0 += r0.x; v1 += r0.y; v2 += r1.x; v3 += r1.y;
            }
            if (RND) {
                v0 = tf32r(v0); v1 = tf32r(v1); v2 = tf32r(v2); v3 = tf32r(v3);
            }
            *(float2*)&C[(size_t)row0 * N + col]       = make_float2(v0, v1);
            *(float2*)&C[(size_t)(row0 + 8) * N + col] = make_float2(v2, v3);
        }
    }
}

// ---------------- Tensor-core flash attention ----------------
#define APITCH 68

__global__ void __launch_bounds__(128) attn_tc(const float* __restrict__ qkv,
                                               float* __restrict__ ctx) {
    extern __shared__ float sm[];
    float* Qs = sm;
    float* Ks = Qs + 64 * APITCH;
    float* Vs = Ks + 64 * APITCH;
    float* Ps = Vs + 64 * APITCH;

    int t = threadIdx.x;
    int warp = t >> 5, lane = t & 31;
    int r4 = lane >> 2, cc = lane & 3;
    int b = blockIdx.z, h = blockIdx.y;
    int s0 = blockIdx.x * 64;
    int wq = warp * 16;

    const float* qbase = qkv + (size_t)(b * 1024 + s0) * 3072 + h * HEAD_D;
    const float* kbase = qkv + (size_t)b * 1024 * 3072 + 1024 + h * HEAD_D;
    const float* vbase = qkv + (size_t)b * 1024 * 3072 + 2048 + h * HEAD_D;

    #pragma unroll
    for (int p = 0; p < 8; ++p) {
        int j = t + 128 * p;
        int row = j >> 4, c4 = j & 15;
        *(float4*)&Qs[row * APITCH + c4 * 4] =
            tf32r4(*(const float4*)(qbase + (size_t)row * 3072 + c4 * 4));
    }

    float mr_lo = -1e30f, mr_hi = -1e30f, l_lo = 0.f, l_hi = 0.f;
    float oacc[8][4];
    #pragma unroll
    for (int i = 0; i < 8; ++i)
        #pragma unroll
        for (int j = 0; j < 4; ++j) oacc[i][j] = 0.f;
    const float scale = 0.125f;

    for (int j0 = 0; j0 < 1024; j0 += 64) {
        __syncthreads();
        #pragma unroll
        for (int p = 0; p < 8; ++p) {
            int j = t + 128 * p;
            int row = j >> 4, c4 = j & 15;
            *(float4*)&Ks[row * APITCH + c4 * 4] =
                tf32r4(*(const float4*)(kbase + (size_t)(j0 + row) * 3072 + c4 * 4));
            *(float4*)&Vs[row * APITCH + c4 * 4] =
                tf32r4(*(const float4*)(vbase + (size_t)(j0 + row) * 3072 + c4 * 4));
        }
        __syncthreads();

        float sacc[8][4];
        #pragma unroll
        for (int i = 0; i < 8; ++i)
            #pragma unroll
            for (int j = 0; j < 4; ++j) sacc[i][j] = 0.f;

        #pragma unroll
        for (int kk = 0; kk < 8; ++kk) {
            int k0 = kk * 8;
            uint32_t a0 = __float_as_uint(Qs[(wq + r4)     * APITCH + k0 + cc]);
            uint32_t a1 = __float_as_uint(Qs[(wq + r4 + 8) * APITCH + k0 + cc]);
            uint32_t a2 = __float_as_uint(Qs[(wq + r4)     * APITCH + k0 + cc + 4]);
            uint32_t a3 = __float_as_uint(Qs[(wq + r4 + 8) * APITCH + k0 + cc + 4]);
            #pragma unroll
            for (int nt = 0; nt < 8; ++nt) {
                uint32_t b0 = __float_as_uint(Ks[(nt * 8 + r4) * APITCH + k0 + cc]);
                uint32_t b1 = __float_as_uint(Ks[(nt * 8 + r4) * APITCH + k0 + cc + 4]);
                mma_tf32(sacc[nt], a0, a1, a2, a3, b0, b1);
            }
        }

        float mlo = -1e30f, mhi = -1e30f;
        #pragma unroll
        for (int nt = 0; nt < 8; ++nt) {
            sacc[nt][0] *= scale; sacc[nt][1] *= scale;
            sacc[nt][2] *= scale; sacc[nt][3] *= scale;
            mlo = fmaxf(mlo, fmaxf(sacc[nt][0], sacc[nt][1]));
            mhi = fmaxf(mhi, fmaxf(sacc[nt][2], sacc[nt][3]));
        }
        mlo = fmaxf(mlo, __shfl_xor_sync(0xffffffffu, mlo, 1));
        mlo = fmaxf(mlo, __shfl_xor_sync(0xffffffffu, mlo, 2));
        mhi = fmaxf(mhi, __shfl_xor_sync(0xffffffffu, mhi, 1));
        mhi = fmaxf(mhi, __shfl_xor_sync(0xffffffffu, mhi, 2));
        float mn_lo = fmaxf(mr_lo, mlo), mn_hi = fmaxf(mr_hi, mhi);
        float al_lo = __expf(mr_lo - mn_lo), al_hi = __expf(mr_hi - mn_hi);

        float ps_lo = 0.f, ps_hi = 0.f;
        #pragma unroll
        for (int nt = 0; nt < 8; ++nt) {
            float p0 = __expf(sacc[nt][0] - mn_lo);
            float p1 = __expf(sacc[nt][1] - mn_lo);
            float p2 = __expf(sacc[nt][2] - mn_hi);
            float p3 = __expf(sacc[nt][3] - mn_hi);
            ps_lo += p0 + p1; ps_hi += p2 + p3;
            int colb = nt * 8 + cc * 2;
            Ps[(wq + r4)     * APITCH + colb]     = tf32r(p0);
            Ps[(wq + r4)     * APITCH + colb + 1] = tf32r(p1);
            Ps[(wq + r4 + 8) * APITCH + colb]     = tf32r(p2);
            Ps[(wq + r4 + 8) * APITCH + colb + 1] = tf32r(p3);
        }
        ps_lo += __shfl_xor_sync(0xffffffffu, ps_lo, 1);
        ps_lo += __shfl_xor_sync(0xffffffffu, ps_lo, 2);
        ps_hi += __shfl_xor_sync(0xffffffffu, ps_hi, 1);
        ps_hi += __shfl_xor_sync(0xffffffffu, ps_hi, 2);
        l_lo = l_lo * al_lo + ps_lo;
        l_hi = l_hi * al_hi + ps_hi;
        mr_lo = mn_lo; mr_hi = mn_hi;
        #pragma unroll
        for (int nt = 0; nt < 8; ++nt) {
            oacc[nt][0] *= al_lo; oacc[nt][1] *= al_lo;
            oacc[nt][2] *= al_hi; oacc[nt][3] *= al_hi;
        }
        __syncwarp();

        #pragma unroll
        for (int kk = 0; kk < 8; ++kk) {
            int k0 = kk * 8;
            uint32_t a0 = __float_as_uint(Ps[(wq + r4)     * APITCH + k0 + cc]);
            uint32_t a1 = __float_as_uint(Ps[(wq + r4 + 8) * APITCH + k0 + cc]);
            uint32_t a2 = __float_as_uint(Ps[(wq + r4)     * APITCH + k0 + cc + 4]);
            uint32_t a3 = __float_as_uint(Ps[(wq + r4 + 8) * APITCH + k0 + cc + 4]);
            #pragma unroll
            for (int nt = 0; nt < 8; ++nt) {
                uint32_t b0 = __float_as_uint(Vs[(k0 + cc)     * APITCH + nt * 8 + r4]);
                uint32_t b1 = __float_as_uint(Vs[(k0 + cc + 4) * APITCH + nt * 8 + r4]);
                mma_tf32(oacc[nt], a0, a1, a2, a3, b0, b1);
            }
        }
    }

    float il_lo = 1.f / l_lo, il_hi = 1.f / l_hi;
    int row_lo = b * 1024 + s0 + wq + r4;
    #pragma unroll
    for (int nt = 0; nt < 8; ++nt) {
        int col = h * HEAD_D + nt * 8 + cc * 2;
        *(float2*)&ctx[(size_t)row_lo * D_MODEL + col] =
            make_float2(tf32r(oacc[nt][0] * il_lo), tf32r(oacc[nt][1] * il_lo));
        *(float2*)&ctx[(size_t)(row_lo + 8) * D_MODEL + col] =
            make_float2(tf32r(oacc[nt][2] * il_hi), tf32r(oacc[nt][3] * il_hi));
    }
}

// ---------------- launch ----------------
extern "C" void kernel_launch(void* const* d_in, const int* in_sizes, int n_in,
                              void* d_out, int out_size) {
    const float* x      = (const float*)d_in[0];
    const float* qkv_w  = (const float*)d_in[1];
    const float* qkv_b  = (const float*)d_in[2];
    const float* proj_w = (const float*)d_in[3];
    const float* proj_b = (const float*)d_in[4];
    const float* fc1_w  = (const float*)d_in[5];
    const float* fc1_b  = (const float*)d_in[6];
    const float* fc2_w  = (const float*)d_in[7];
    const float* fc2_b  = (const float*)d_in[8];
    const float* ln1_g  = (const float*)d_in[9];
    const float* ln1_b  = (const float*)d_in[10];
    const float* ln2_g  = (const float*)d_in[11];
    const float* ln2_b  = (const float*)d_in[12];
    float* out = (float*)d_out;

    float *h, *qkv, *ctx, *x2, *ff, *wq, *wp, *w1, *w2;
    cudaGetSymbolAddress((void**)&h,   g_h);
    cudaGetSymbolAddress((void**)&qkv, g_qkv);
    cudaGetSymbolAddress((void**)&ctx, g_ctx);
    cudaGetSymbolAddress((void**)&x2,  g_x2);
    cudaGetSymbolAddress((void**)&ff,  g_ff);
    cudaGetSymbolAddress((void**)&wq,  g_wq);
    cudaGetSymbolAddress((void**)&wp,  g_wp);
    cudaGetSymbolAddress((void**)&w1,  g_w1);
    cudaGetSymbolAddress((void**)&w2,  g_w2);

    int attn_smem = 4 * 64 * APITCH * (int)sizeof(float);
    cudaFuncSetAttribute(attn_tc, cudaFuncAttributeMaxDynamicSharedMemorySize,
                         attn_smem);
    int gemm_smem = STAGES * STAGE_BYTES;   // 81920
    cudaFuncSetAttribute(gemm_cp<0,0>, cudaFuncAttributeMaxDynamicSharedMemorySize, gemm_smem);
    cudaFuncSetAttribute(gemm_cp<2,0>, cudaFuncAttributeMaxDynamicSharedMemorySize, gemm_smem);
    cudaFuncSetAttribute(gemm_cp<1,1>, cudaFuncAttributeMaxDynamicSharedMemorySize, gemm_smem);

    round_w<<<(3*D_MODEL*D_MODEL/4 + 255)/256, 256>>>(qkv_w, wq, 3*D_MODEL*D_MODEL/4);
    round_w<<<(D_MODEL*D_MODEL/4 + 255)/256, 256>>>(proj_w, wp, D_MODEL*D_MODEL/4);
    round_w<<<(FF_DIM*D_MODEL/4 + 255)/256, 256>>>(fc1_w, w1, FF_DIM*D_MODEL/4);
    round_w<<<(D_MODEL*FF_DIM/4 + 255)/256, 256>>>(fc2_w, w2, D_MODEL*FF_DIM/4);

    ln_kernel<<<N_TOK, 256>>>(x, ln1_g, ln1_b, h);
    gemm_cp<0,0><<<dim3(3 * D_MODEL / BN, N_TOK / BM), 128, gemm_smem>>>(
        h, wq, qkv_b, nullptr, qkv, N_TOK, 3 * D_MODEL, D_MODEL);
    attn_tc<<<dim3(1024 / 64, N_HEAD, 8), 128, attn_smem>>>(qkv, ctx);
    gemm_cp<2,0><<<dim3(D_MODEL / BN, N_TOK / BM), 128, gemm_smem>>>(
        ctx, wp, proj_b, x, x2, N_TOK, D_MODEL, D_MODEL);
    ln_kernel<<<N_TOK, 256>>>(x2, ln2_g, ln2_b, h);
    gemm_cp<1,1><<<dim3(FF_DIM / BN, N_TOK / BM), 128, gemm_smem>>>(
        h, w1, fc1_b, nullptr, ff, N_TOK, FF_DIM, D_MODEL);
    gemm_cp<2,0><<<dim3(D_MODEL / BN, N_TOK / BM), 128, gemm_smem>>>(
        ff, w2, fc2_b, x2, out, N_TOK, D_MODEL, FF_DIM);
}

// round 7
// speedup vs baseline: 1.3428x; 1.3428x over previous
#include <cuda_runtime.h>
#include <cuda_fp16.h>
#include <math.h>
#include <stdint.h>

#define D_MODEL 1024
#define N_TOK   8192
#define FF_DIM  4096
#define N_HEAD  16
#define HEAD_D  64

__device__ __half g_h  [N_TOK * D_MODEL];
__device__ float  g_qkv[N_TOK * 3 * D_MODEL];
__device__ __half g_ctx[N_TOK * D_MODEL];
__device__ float  g_x2 [N_TOK * D_MODEL];
__device__ __half g_ff [N_TOK * FF_DIM];
__device__ __half g_wq[3 * D_MODEL * D_MODEL];
__device__ __half g_wp[D_MODEL * D_MODEL];
__device__ __half g_w1[FF_DIM * D_MODEL];
__device__ __half g_w2[D_MODEL * FF_DIM];

// ---------------- helpers ----------------
__device__ __forceinline__ float gelu_exact(float v) {
    return 0.5f * v * (1.0f + erff(v * 0.70710678118654752440f));
}
__device__ __forceinline__ float tf32r(float x) {
    uint32_t u;
    asm("cvt.rna.tf32.f32 %0, %1;" : "=r"(u) : "f"(x));
    return __uint_as_float(u);
}
__device__ __forceinline__ float4 tf32r4(float4 v) {
    v.x = tf32r(v.x); v.y = tf32r(v.y); v.z = tf32r(v.z); v.w = tf32r(v.w);
    return v;
}
__device__ __forceinline__ void mma_tf32(float d[4], uint32_t a0, uint32_t a1,
                                         uint32_t a2, uint32_t a3,
                                         uint32_t b0, uint32_t b1) {
    asm volatile(
        "mma.sync.aligned.m16n8k8.row.col.f32.tf32.tf32.f32 "
        "{%0,%1,%2,%3}, {%4,%5,%6,%7}, {%8,%9}, {%0,%1,%2,%3};\n"
        : "+f"(d[0]), "+f"(d[1]), "+f"(d[2]), "+f"(d[3])
        : "r"(a0), "r"(a1), "r"(a2), "r"(a3), "r"(b0), "r"(b1));
}
__device__ __forceinline__ void mma_f16(float d[4], uint32_t a0, uint32_t a1,
                                        uint32_t a2, uint32_t a3,
                                        uint32_t b0, uint32_t b1) {
    asm volatile(
        "mma.sync.aligned.m16n8k16.row.col.f32.f16.f16.f32 "
        "{%0,%1,%2,%3}, {%4,%5,%6,%7}, {%8,%9}, {%0,%1,%2,%3};\n"
        : "+f"(d[0]), "+f"(d[1]), "+f"(d[2]), "+f"(d[3])
        : "r"(a0), "r"(a1), "r"(a2), "r"(a3), "r"(b0), "r"(b1));
}
__device__ __forceinline__ void ldsm4(uint32_t& r0, uint32_t& r1, uint32_t& r2,
                                      uint32_t& r3, uint32_t addr) {
    asm volatile("ldmatrix.sync.aligned.m8n8.x4.shared.b16 {%0,%1,%2,%3}, [%4];"
                 : "=r"(r0), "=r"(r1), "=r"(r2), "=r"(r3) : "r"(addr));
}
__device__ __forceinline__ void cp16(uint32_t smem, const void* g) {
    asm volatile("cp.async.cg.shared.global [%0], [%1], 16;" :: "r"(smem), "l"(g));
}
__device__ __forceinline__ void cp_commit() {
    asm volatile("cp.async.commit_group;");
}
__device__ __forceinline__ void cp_wait2() {
    asm volatile("cp.async.wait_group 2;");
}

// ---------------- weight pre-convert fp32 -> fp16 ----------------
__global__ void __launch_bounds__(256) conv_w(const float* __restrict__ in,
                                              __half* __restrict__ out, int n4) {
    int i = blockIdx.x * 256 + threadIdx.x;
    if (i < n4) {
        float4 v = ((const float4*)in)[i];
        __half2 lo = __floats2half2_rn(v.x, v.y);
        __half2 hi = __floats2half2_rn(v.z, v.w);
        uint2 o;
        o.x = *(uint32_t*)&lo;
        o.y = *(uint32_t*)&hi;
        ((uint2*)out)[i] = o;
    }
}

// ---------------- LayerNorm (fp16 output) ----------------
__global__ void __launch_bounds__(256) ln_kernel(const float* __restrict__ x,
                                                 const float* __restrict__ g,
                                                 const float* __restrict__ b,
                                                 __half* __restrict__ out) {
    int row = blockIdx.x;
    int t = threadIdx.x;
    const float* xr = x + (size_t)row * D_MODEL;
    float4 xv = ((const float4*)xr)[t];

    float s  = xv.x + xv.y + xv.z + xv.w;
    float sq = xv.x*xv.x + xv.y*xv.y + xv.z*xv.z + xv.w*xv.w;
    #pragma unroll
    for (int o = 16; o > 0; o >>= 1) {
        s  += __shfl_xor_sync(0xffffffffu, s,  o);
        sq += __shfl_xor_sync(0xffffffffu, sq, o);
    }
    __shared__ float red[2][8];
    int wid = t >> 5, lane = t & 31;
    if (lane == 0) { red[0][wid] = s; red[1][wid] = sq; }
    __syncthreads();
    float tot = 0.f, tot2 = 0.f;
    #pragma unroll
    for (int w = 0; w < 8; ++w) { tot += red[0][w]; tot2 += red[1][w]; }
    float mu = tot * (1.0f / D_MODEL);
    float var = tot2 * (1.0f / D_MODEL) - mu * mu;
    float rstd = rsqrtf(var + 1e-6f);

    float4 gv = ((const float4*)g)[t];
    float4 bv = ((const float4*)b)[t];
    float v0 = (xv.x - mu) * rstd * gv.x + bv.x;
    float v1 = (xv.y - mu) * rstd * gv.y + bv.y;
    float v2 = (xv.z - mu) * rstd * gv.z + bv.z;
    float v3 = (xv.w - mu) * rstd * gv.w + bv.w;
    __half2 lo = __floats2half2_rn(v0, v1);
    __half2 hi = __floats2half2_rn(v2, v3);
    uint2 o;
    o.x = *(uint32_t*)&lo;
    o.y = *(uint32_t*)&hi;
    ((uint2*)(out + (size_t)row * D_MODEL))[t] = o;
}

// ---------------- FP16 GEMM: cp.async 4-stage + ldmatrix + m16n8k16 --------
// C[M,N] = A[M,K] @ B[N,K]^T + bias (+epi). A,B fp16 k-major, acc fp32.
#define BM 128
#define BN 128
#define BKH 32                   // K halves per tile (64 bytes)
#define PITCHB 80                // bytes per smem row (64 data + 16 pad)
#define STAGES 4
#define STAGE_BYTES (2 * BM * PITCHB)   // A + B = 20480
#define B_OFF (BM * PITCHB)             // 10240

template<int EPI, int OUTHALF>
__global__ void __launch_bounds__(256, 2) gemm_h(const __half* __restrict__ A,
                                                 const __half* __restrict__ Bw,
                                                 const float* __restrict__ bias,
                                                 const float* __restrict__ res,
                                                 void* __restrict__ Cout,
                                                 int M, int N, int K) {
    extern __shared__ char smraw[];
    uint32_t su = (uint32_t)__cvta_generic_to_shared(smraw);

    int tid = threadIdx.x;
    int m0 = blockIdx.y * BM;
    int n0 = blockIdx.x * BN;
    int warp = tid >> 5, lane = tid & 31;
    int wm = (warp & 1) * 64;
    int wn = (warp >> 1) * 32;
    int r4 = lane >> 2, cc = lane & 3;

    float acc[4][4][4];
    #pragma unroll
    for (int i = 0; i < 4; ++i)
        #pragma unroll
        for (int j = 0; j < 4; ++j)
            #pragma unroll
            for (int k = 0; k < 4; ++k) acc[i][j][k] = 0.f;

    // loader: row = tid&127, chunk = tid>>7 (two 16B chunks per thread per mat)
    int row = tid & 127;
    int chk = tid >> 7;
    const __half* Ap = A  + (size_t)(m0 + row) * K + chk * 16;
    const __half* Bp = Bw + (size_t)(n0 + row) * K + chk * 16;
    uint32_t dA = (uint32_t)(row * PITCHB + chk * 32);

    // ldmatrix addressing
    uint32_t aAddr = su + (uint32_t)((wm + (lane & 15)) * PITCHB + (lane >> 4) * 16);
    uint32_t bAddr = su + B_OFF +
        (uint32_t)((wn + (lane & 7) + ((lane >> 4) << 3)) * PITCHB +
                   ((lane >> 3) & 1) * 16);

    int ntiles = K / BKH;

    #pragma unroll
    for (int s = 0; s < STAGES - 1; ++s) {
        uint32_t sb = su + s * STAGE_BYTES;
        const __half* a = Ap + s * BKH;
        const __half* b = Bp + s * BKH;
        cp16(sb + dA, a);            cp16(sb + dA + 16, a + 8);
        cp16(sb + B_OFF + dA, b);    cp16(sb + B_OFF + dA + 16, b + 8);
        cp_commit();
    }

    for (int t = 0; t < ntiles; ++t) {
        cp_wait2();
        __syncthreads();

        int tp = t + STAGES - 1;
        if (tp < ntiles) {
            uint32_t sb = su + (tp & (STAGES - 1)) * STAGE_BYTES;
            const __half* a = Ap + tp * BKH;
            const __half* b = Bp + tp * BKH;
            cp16(sb + dA, a);            cp16(sb + dA + 16, a + 8);
            cp16(sb + B_OFF + dA, b);    cp16(sb + B_OFF + dA + 16, b + 8);
        }
        cp_commit();

        uint32_t stg = (t & (STAGES - 1)) * STAGE_BYTES;
        #pragma unroll
        for (int ks = 0; ks < 2; ++ks) {
            uint32_t kof = stg + ks * 32;
            uint32_t af[4][4], bf[4][2];
            #pragma unroll
            for (int mt = 0; mt < 4; ++mt)
                ldsm4(af[mt][0], af[mt][1], af[mt][2], af[mt][3],
                      aAddr + kof + mt * (16 * PITCHB));
            ldsm4(bf[0][0], bf[0][1], bf[1][0], bf[1][1], bAddr + kof);
            ldsm4(bf[2][0], bf[2][1], bf[3][0], bf[3][1],
                  bAddr + kof + 16 * PITCHB);
            #pragma unroll
            for (int mt = 0; mt < 4; ++mt)
                #pragma unroll
                for (int nt = 0; nt < 4; ++nt)
                    mma_f16(acc[mt][nt], af[mt][0], af[mt][1], af[mt][2], af[mt][3],
                            bf[nt][0], bf[nt][1]);
        }
    }

    #pragma unroll
    for (int mt = 0; mt < 4; ++mt) {
        int row0 = m0 + wm + mt * 16 + r4;
        #pragma unroll
        for (int nt = 0; nt < 4; ++nt) {
            int col = n0 + wn + nt * 8 + cc * 2;
            float b0v = bias[col], b1v = bias[col + 1];
            float v0 = acc[mt][nt][0] + b0v;
            float v1 = acc[mt][nt][1] + b1v;
            float v2 = acc[mt][nt][2] + b0v;
            float v3 = acc[mt][nt][3] + b1v;
            if (EPI == 1) {
                v0 = gelu_exact(v0); v1 = gelu_exact(v1);
                v2 = gelu_exact(v2); v3 = gelu_exact(v3);
            }
            if (EPI == 2) {
                float2 r0 = *(const float2*)&res[(size_t)row0 * N + col];
                float2 r1 = *(const float2*)&res[(size_t)(row0 + 8) * N + col];
                v0 += r0.x; v1 += r0.y; v2 += r1.x; v3 += r1.y;
            }
            if (OUTHALF) {
                __half* Ch = (__half*)Cout;
                *(__half2*)&Ch[(size_t)row0 * N + col]       = __floats2half2_rn(v0, v1);
                *(__half2*)&Ch[(size_t)(row0 + 8) * N + col] = __floats2half2_rn(v2, v3);
            } else {
                float* Cf = (float*)Cout;
                *(float2*)&Cf[(size_t)row0 * N + col]       = make_float2(v0, v1);
                *(float2*)&Cf[(size_t)(row0 + 8) * N + col] = make_float2(v2, v3);
            }
        }
    }
}

// ---------------- Tensor-core flash attention (tf32 mma, half output) ------
#define APITCH 68

__global__ void __launch_bounds__(128) attn_tc(const float* __restrict__ qkv,
                                               __half* __restrict__ ctx) {
    extern __shared__ float sm[];
    float* Qs = sm;
    float* Ks = Qs + 64 * APITCH;
    float* Vs = Ks + 64 * APITCH;
    float* Ps = Vs + 64 * APITCH;

    int t = threadIdx.x;
    int warp = t >> 5, lane = t & 31;
    int r4 = lane >> 2, cc = lane & 3;
    int b = blockIdx.z, h = blockIdx.y;
    int s0 = blockIdx.x * 64;
    int wq = warp * 16;

    const float* qbase = qkv + (size_t)(b * 1024 + s0) * 3072 + h * HEAD_D;
    const float* kbase = qkv + (size_t)b * 1024 * 3072 + 1024 + h * HEAD_D;
    const float* vbase = qkv + (size_t)b * 1024 * 3072 + 2048 + h * HEAD_D;

    #pragma unroll
    for (int p = 0; p < 8; ++p) {
        int j = t + 128 * p;
        int row = j >> 4, c4 = j & 15;
        *(float4*)&Qs[row * APITCH + c4 * 4] =
            tf32r4(*(const float4*)(qbase + (size_t)row * 3072 + c4 * 4));
    }

    float mr_lo = -1e30f, mr_hi = -1e30f, l_lo = 0.f, l_hi = 0.f;
    float oacc[8][4];
    #pragma unroll
    for (int i = 0; i < 8; ++i)
        #pragma unroll
        for (int j = 0; j < 4; ++j) oacc[i][j] = 0.f;
    const float scale = 0.125f;

    for (int j0 = 0; j0 < 1024; j0 += 64) {
        __syncthreads();
        #pragma unroll
        for (int p = 0; p < 8; ++p) {
            int j = t + 128 * p;
            int row = j >> 4, c4 = j & 15;
            *(float4*)&Ks[row * APITCH + c4 * 4] =
                tf32r4(*(const float4*)(kbase + (size_t)(j0 + row) * 3072 + c4 * 4));
            *(float4*)&Vs[row * APITCH + c4 * 4] =
                tf32r4(*(const float4*)(vbase + (size_t)(j0 + row) * 3072 + c4 * 4));
        }
        __syncthreads();

        float sacc[8][4];
        #pragma unroll
        for (int i = 0; i < 8; ++i)
            #pragma unroll
            for (int j = 0; j < 4; ++j) sacc[i][j] = 0.f;

        #pragma unroll
        for (int kk = 0; kk < 8; ++kk) {
            int k0 = kk * 8;
            uint32_t a0 = __float_as_uint(Qs[(wq + r4)     * APITCH + k0 + cc]);
            uint32_t a1 = __float_as_uint(Qs[(wq + r4 + 8) * APITCH + k0 + cc]);
            uint32_t a2 = __float_as_uint(Qs[(wq + r4)     * APITCH + k0 + cc + 4]);
            uint32_t a3 = __float_as_uint(Qs[(wq + r4 + 8) * APITCH + k0 + cc + 4]);
            #pragma unroll
            for (int nt = 0; nt < 8; ++nt) {
                uint32_t b0 = __float_as_uint(Ks[(nt * 8 + r4) * APITCH + k0 + cc]);
                uint32_t b1 = __float_as_uint(Ks[(nt * 8 + r4) * APITCH + k0 + cc + 4]);
                mma_tf32(sacc[nt], a0, a1, a2, a3, b0, b1);
            }
        }

        float mlo = -1e30f, mhi = -1e30f;
        #pragma unroll
        for (int nt = 0; nt < 8; ++nt) {
            sacc[nt][0] *= scale; sacc[nt][1] *= scale;
            sacc[nt][2] *= scale; sacc[nt][3] *= scale;
            mlo = fmaxf(mlo, fmaxf(sacc[nt][0], sacc[nt][1]));
            mhi = fmaxf(mhi, fmaxf(sacc[nt][2], sacc[nt][3]));
        }
        mlo = fmaxf(mlo, __shfl_xor_sync(0xffffffffu, mlo, 1));
        mlo = fmaxf(mlo, __shfl_xor_sync(0xffffffffu, mlo, 2));
        mhi = fmaxf(mhi, __shfl_xor_sync(0xffffffffu, mhi, 1));
        mhi = fmaxf(mhi, __shfl_xor_sync(0xffffffffu, mhi, 2));
        float mn_lo = fmaxf(mr_lo, mlo), mn_hi = fmaxf(mr_hi, mhi);
        float al_lo = __expf(mr_lo - mn_lo), al_hi = __expf(mr_hi - mn_hi);

        float ps_lo = 0.f, ps_hi = 0.f;
        #pragma unroll
        for (int nt = 0; nt < 8; ++nt) {
            float p0 = __expf(sacc[nt][0] - mn_lo);
            float p1 = __expf(sacc[nt][1] - mn_lo);
            float p2 = __expf(sacc[nt][2] - mn_hi);
            float p3 = __expf(sacc[nt][3] - mn_hi);
            ps_lo += p0 + p1; ps_hi += p2 + p3;
            int colb = nt * 8 + cc * 2;
            Ps[(wq + r4)     * APITCH + colb]     = tf32r(p0);
            Ps[(wq + r4)     * APITCH + colb + 1] = tf32r(p1);
            Ps[(wq + r4 + 8) * APITCH + colb]     = tf32r(p2);
            Ps[(wq + r4 + 8) * APITCH + colb + 1] = tf32r(p3);
        }
        ps_lo += __shfl_xor_sync(0xffffffffu, ps_lo, 1);
        ps_lo += __shfl_xor_sync(0xffffffffu, ps_lo, 2);
        ps_hi += __shfl_xor_sync(0xffffffffu, ps_hi, 1);
        ps_hi += __shfl_xor_sync(0xffffffffu, ps_hi, 2);
        l_lo = l_lo * al_lo + ps_lo;
        l_hi = l_hi * al_hi + ps_hi;
        mr_lo = mn_lo; mr_hi = mn_hi;
        #pragma unroll
        for (int nt = 0; nt < 8; ++nt) {
            oacc[nt][0] *= al_lo; oacc[nt][1] *= al_lo;
            oacc[nt][2] *= al_hi; oacc[nt][3] *= al_hi;
        }
        __syncwarp();

        #pragma unroll
        for (int kk = 0; kk < 8; ++kk) {
            int k0 = kk * 8;
            uint32_t a0 = __float_as_uint(Ps[(wq + r4)     * APITCH + k0 + cc]);
            uint32_t a1 = __float_as_uint(Ps[(wq + r4 + 8) * APITCH + k0 + cc]);
            uint32_t a2 = __float_as_uint(Ps[(wq + r4)     * APITCH + k0 + cc + 4]);
            uint32_t a3 = __float_as_uint(Ps[(wq + r4 + 8) * APITCH + k0 + cc + 4]);
            #pragma unroll
            for (int nt = 0; nt < 8; ++nt) {
                uint32_t b0 = __float_as_uint(Vs[(k0 + cc)     * APITCH + nt * 8 + r4]);
                uint32_t b1 = __float_as_uint(Vs[(k0 + cc + 4) * APITCH + nt * 8 + r4]);
                mma_tf32(oacc[nt], a0, a1, a2, a3, b0, b1);
            }
        }
    }

    float il_lo = 1.f / l_lo, il_hi = 1.f / l_hi;
    int row_lo = b * 1024 + s0 + wq + r4;
    #pragma unroll
    for (int nt = 0; nt < 8; ++nt) {
        int col = h * HEAD_D + nt * 8 + cc * 2;
        *(__half2*)&ctx[(size_t)row_lo * D_MODEL + col] =
            __floats2half2_rn(oacc[nt][0] * il_lo, oacc[nt][1] * il_lo);
        *(__half2*)&ctx[(size_t)(row_lo + 8) * D_MODEL + col] =
            __floats2half2_rn(oacc[nt][2] * il_hi, oacc[nt][3] * il_hi);
    }
}

// ---------------- launch ----------------
extern "C" void kernel_launch(void* const* d_in, const int* in_sizes, int n_in,
                              void* d_out, int out_size) {
    const float* x      = (const float*)d_in[0];
    const float* qkv_w  = (const float*)d_in[1];
    const float* qkv_b  = (const float*)d_in[2];
    const float* proj_w = (const float*)d_in[3];
    const float* proj_b = (const float*)d_in[4];
    const float* fc1_w  = (const float*)d_in[5];
    const float* fc1_b  = (const float*)d_in[6];
    const float* fc2_w  = (const float*)d_in[7];
    const float* fc2_b  = (const float*)d_in[8];
    const float* ln1_g  = (const float*)d_in[9];
    const float* ln1_b  = (const float*)d_in[10];
    const float* ln2_g  = (const float*)d_in[11];
    const float* ln2_b  = (const float*)d_in[12];
    float* out = (float*)d_out;

    __half *h, *ctx, *ff, *wq, *wp, *w1, *w2;
    float *qkv, *x2;
    cudaGetSymbolAddress((void**)&h,   g_h);
    cudaGetSymbolAddress((void**)&qkv, g_qkv);
    cudaGetSymbolAddress((void**)&ctx, g_ctx);
    cudaGetSymbolAddress((void**)&x2,  g_x2);
    cudaGetSymbolAddress((void**)&ff,  g_ff);
    cudaGetSymbolAddress((void**)&wq,  g_wq);
    cudaGetSymbolAddress((void**)&wp,  g_wp);
    cudaGetSymbolAddress((void**)&w1,  g_w1);
    cudaGetSymbolAddress((void**)&w2,  g_w2);

    int attn_smem = 4 * 64 * APITCH * (int)sizeof(float);
    cudaFuncSetAttribute(attn_tc, cudaFuncAttributeMaxDynamicSharedMemorySize,
                         attn_smem);
    int gemm_smem = STAGES * STAGE_BYTES;   // 81920
    cudaFuncSetAttribute(gemm_h<0,0>, cudaFuncAttributeMaxDynamicSharedMemorySize, gemm_smem);
    cudaFuncSetAttribute(gemm_h<2,0>, cudaFuncAttributeMaxDynamicSharedMemorySize, gemm_smem);
    cudaFuncSetAttribute(gemm_h<1,1>, cudaFuncAttributeMaxDynamicSharedMemorySize, gemm_smem);

    conv_w<<<(3*D_MODEL*D_MODEL/4 + 255)/256, 256>>>(qkv_w, wq, 3*D_MODEL*D_MODEL/4);
    conv_w<<<(D_MODEL*D_MODEL/4 + 255)/256, 256>>>(proj_w, wp, D_MODEL*D_MODEL/4);
    conv_w<<<(FF_DIM*D_MODEL/4 + 255)/256, 256>>>(fc1_w, w1, FF_DIM*D_MODEL/4);
    conv_w<<<(D_MODEL*FF_DIM/4 + 255)/256, 256>>>(fc2_w, w2, D_MODEL*FF_DIM/4);

    ln_kernel<<<N_TOK, 256>>>(x, ln1_g, ln1_b, h);
    gemm_h<0,0><<<dim3(3 * D_MODEL / BN, N_TOK / BM), 256, gemm_smem>>>(
        h, wq, qkv_b, nullptr, qkv, N_TOK, 3 * D_MODEL, D_MODEL);
    attn_tc<<<dim3(1024 / 64, N_HEAD, 8), 128, attn_smem>>>(qkv, ctx);
    gemm_h<2,0><<<dim3(D_MODEL / BN, N_TOK / BM), 256, gemm_smem>>>(
        ctx, wp, proj_b, x, x2, N_TOK, D_MODEL, D_MODEL);
    ln_kernel<<<N_TOK, 256>>>(x2, ln2_g, ln2_b, h);
    gemm_h<1,1><<<dim3(FF_DIM / BN, N_TOK / BM), 256, gemm_smem>>>(
        h, w1, fc1_b, nullptr, ff, N_TOK, FF_DIM, D_MODEL);
    gemm_h<2,0><<<dim3(D_MODEL / BN, N_TOK / BM), 256, gemm_smem>>>(
        ff, w2, fc2_b, x2, out, N_TOK, D_MODEL, FF_DIM);
}

// round 8
// speedup vs baseline: 1.8254x; 1.3594x over previous
#include <cuda_runtime.h>
#include <cuda_fp16.h>
#include <math.h>
#include <stdint.h>

#define D_MODEL 1024
#define N_TOK   8192
#define FF_DIM  4096
#define N_HEAD  16
#define HEAD_D  64

__device__ __half g_h  [N_TOK * D_MODEL];
__device__ __half g_qkv[N_TOK * 3 * D_MODEL];
__device__ __half g_ctx[N_TOK * D_MODEL];
__device__ float  g_x2 [N_TOK * D_MODEL];
__device__ __half g_ff [N_TOK * FF_DIM];
__device__ __half g_wq[3 * D_MODEL * D_MODEL];
__device__ __half g_wp[D_MODEL * D_MODEL];
__device__ __half g_w1[FF_DIM * D_MODEL];
__device__ __half g_w2[D_MODEL * FF_DIM];

// ---------------- helpers ----------------
__device__ __forceinline__ float gelu_exact(float v) {
    return 0.5f * v * (1.0f + erff(v * 0.70710678118654752440f));
}
__device__ __forceinline__ void mma_f16(float d[4], uint32_t a0, uint32_t a1,
                                        uint32_t a2, uint32_t a3,
                                        uint32_t b0, uint32_t b1) {
    asm volatile(
        "mma.sync.aligned.m16n8k16.row.col.f32.f16.f16.f32 "
        "{%0,%1,%2,%3}, {%4,%5,%6,%7}, {%8,%9}, {%0,%1,%2,%3};\n"
        : "+f"(d[0]), "+f"(d[1]), "+f"(d[2]), "+f"(d[3])
        : "r"(a0), "r"(a1), "r"(a2), "r"(a3), "r"(b0), "r"(b1));
}
__device__ __forceinline__ void ldsm4(uint32_t& r0, uint32_t& r1, uint32_t& r2,
                                      uint32_t& r3, uint32_t addr) {
    asm volatile("ldmatrix.sync.aligned.m8n8.x4.shared.b16 {%0,%1,%2,%3}, [%4];"
                 : "=r"(r0), "=r"(r1), "=r"(r2), "=r"(r3) : "r"(addr));
}
__device__ __forceinline__ void cp16(uint32_t smem, const void* g) {
    asm volatile("cp.async.cg.shared.global [%0], [%1], 16;" :: "r"(smem), "l"(g));
}
__device__ __forceinline__ void cp_commit() {
    asm volatile("cp.async.commit_group;");
}
__device__ __forceinline__ void cp_wait2() {
    asm volatile("cp.async.wait_group 2;");
}
__device__ __forceinline__ uint32_t pack2(float a, float b) {
    __half2 h = __floats2half2_rn(a, b);
    return *(uint32_t*)&h;
}

// ---------------- weight pre-convert fp32 -> fp16 ----------------
__global__ void __launch_bounds__(256) conv_w(const float* __restrict__ in,
                                              __half* __restrict__ out, int n4) {
    int i = blockIdx.x * 256 + threadIdx.x;
    if (i < n4) {
        float4 v = ((const float4*)in)[i];
        uint2 o;
        o.x = pack2(v.x, v.y);
        o.y = pack2(v.z, v.w);
        ((uint2*)out)[i] = o;
    }
}

// ---------------- LayerNorm (fp16 output) ----------------
__global__ void __launch_bounds__(256) ln_kernel(const float* __restrict__ x,
                                                 const float* __restrict__ g,
                                                 const float* __restrict__ b,
                                                 __half* __restrict__ out) {
    int row = blockIdx.x;
    int t = threadIdx.x;
    const float* xr = x + (size_t)row * D_MODEL;
    float4 xv = ((const float4*)xr)[t];

    float s  = xv.x + xv.y + xv.z + xv.w;
    float sq = xv.x*xv.x + xv.y*xv.y + xv.z*xv.z + xv.w*xv.w;
    #pragma unroll
    for (int o = 16; o > 0; o >>= 1) {
        s  += __shfl_xor_sync(0xffffffffu, s,  o);
        sq += __shfl_xor_sync(0xffffffffu, sq, o);
    }
    __shared__ float red[2][8];
    int wid = t >> 5, lane = t & 31;
    if (lane == 0) { red[0][wid] = s; red[1][wid] = sq; }
    __syncthreads();
    float tot = 0.f, tot2 = 0.f;
    #pragma unroll
    for (int w = 0; w < 8; ++w) { tot += red[0][w]; tot2 += red[1][w]; }
    float mu = tot * (1.0f / D_MODEL);
    float var = tot2 * (1.0f / D_MODEL) - mu * mu;
    float rstd = rsqrtf(var + 1e-6f);

    float4 gv = ((const float4*)g)[t];
    float4 bv = ((const float4*)b)[t];
    float v0 = (xv.x - mu) * rstd * gv.x + bv.x;
    float v1 = (xv.y - mu) * rstd * gv.y + bv.y;
    float v2 = (xv.z - mu) * rstd * gv.z + bv.z;
    float v3 = (xv.w - mu) * rstd * gv.w + bv.w;
    uint2 o;
    o.x = pack2(v0, v1);
    o.y = pack2(v2, v3);
    ((uint2*)(out + (size_t)row * D_MODEL))[t] = o;
}

// ---------------- FP16 GEMM: 256x128 CTA tile, 512 threads --------
// C[M,N] = A[M,K] @ B[N,K]^T + bias (+epi). Warp tile 64x32.
#define BM2 256
#define BN 128
#define BKH 32                   // K halves per tile (64 bytes)
#define PITCHB 80                // bytes per smem row
#define STAGES 4
#define A_SZ (BM2 * PITCHB)             // 20480
#define STAGE_BYTES (A_SZ + BN * PITCHB)   // 30720

template<int EPI, int OUTHALF>
__global__ void __launch_bounds__(512, 1) gemm_h(const __half* __restrict__ A,
                                                 const __half* __restrict__ Bw,
                                                 const float* __restrict__ bias,
                                                 const float* __restrict__ res,
                                                 void* __restrict__ Cout,
                                                 int M, int N, int K) {
    extern __shared__ char smraw[];
    uint32_t su = (uint32_t)__cvta_generic_to_shared(smraw);

    int tid = threadIdx.x;
    int m0 = blockIdx.y * BM2;
    int n0 = blockIdx.x * BN;
    int warp = tid >> 5, lane = tid & 31;
    int wm = (warp & 3) * 64;
    int wn = (warp >> 2) * 32;
    int r4 = lane >> 2, cc = lane & 3;

    float acc[4][4][4];
    #pragma unroll
    for (int i = 0; i < 4; ++i)
        #pragma unroll
        for (int j = 0; j < 4; ++j)
            #pragma unroll
            for (int k = 0; k < 4; ++k) acc[i][j][k] = 0.f;

    // A loader: row = tid>>1 (0..255), pair = tid&1 -> 2 cp16
    int arow = tid >> 1, apr = tid & 1;
    const __half* Ap = A + (size_t)(m0 + arow) * K + apr * 16;
    uint32_t dA = (uint32_t)(arow * PITCHB + apr * 32);
    // B loader: row = tid>>2 (0..127), chunk = tid&3 -> 1 cp16
    int brow = tid >> 2, bch = tid & 3;
    const __half* Bp = Bw + (size_t)(n0 + brow) * K + bch * 8;
    uint32_t dB = (uint32_t)(A_SZ + brow * PITCHB + bch * 16);

    uint32_t aAddr = su + (uint32_t)((wm + (lane & 15)) * PITCHB + (lane >> 4) * 16);
    uint32_t bAddr = su + A_SZ +
        (uint32_t)((wn + (lane & 7) + ((lane >> 4) << 3)) * PITCHB +
                   ((lane >> 3) & 1) * 16);

    int ntiles = K / BKH;

    #pragma unroll
    for (int s = 0; s < STAGES - 1; ++s) {
        uint32_t sb = su + s * STAGE_BYTES;
        cp16(sb + dA, Ap + s * BKH);
        cp16(sb + dA + 16, Ap + s * BKH + 8);
        cp16(sb + dB, Bp + s * BKH);
        cp_commit();
    }

    for (int t = 0; t < ntiles; ++t) {
        cp_wait2();
        __syncthreads();

        int tp = t + STAGES - 1;
        if (tp < ntiles) {
            uint32_t sb = su + (tp & (STAGES - 1)) * STAGE_BYTES;
            cp16(sb + dA, Ap + tp * BKH);
            cp16(sb + dA + 16, Ap + tp * BKH + 8);
            cp16(sb + dB, Bp + tp * BKH);
        }
        cp_commit();

        uint32_t stg = (t & (STAGES - 1)) * STAGE_BYTES;
        #pragma unroll
        for (int ks = 0; ks < 2; ++ks) {
            uint32_t kof = stg + ks * 32;
            uint32_t af[4][4], bf[4][2];
            #pragma unroll
            for (int mt = 0; mt < 4; ++mt)
                ldsm4(af[mt][0], af[mt][1], af[mt][2], af[mt][3],
                      aAddr + kof + mt * (16 * PITCHB));
            ldsm4(bf[0][0], bf[0][1], bf[1][0], bf[1][1], bAddr + kof);
            ldsm4(bf[2][0], bf[2][1], bf[3][0], bf[3][1],
                  bAddr + kof + 16 * PITCHB);
            #pragma unroll
            for (int mt = 0; mt < 4; ++mt)
                #pragma unroll
                for (int nt = 0; nt < 4; ++nt)
                    mma_f16(acc[mt][nt], af[mt][0], af[mt][1], af[mt][2], af[mt][3],
                            bf[nt][0], bf[nt][1]);
        }
    }

    #pragma unroll
    for (int mt = 0; mt < 4; ++mt) {
        int row0 = m0 + wm + mt * 16 + r4;
        #pragma unroll
        for (int nt = 0; nt < 4; ++nt) {
            int col = n0 + wn + nt * 8 + cc * 2;
            float b0v = bias[col], b1v = bias[col + 1];
            float v0 = acc[mt][nt][0] + b0v;
            float v1 = acc[mt][nt][1] + b1v;
            float v2 = acc[mt][nt][2] + b0v;
            float v3 = acc[mt][nt][3] + b1v;
            if (EPI == 1) {
                v0 = gelu_exact(v0); v1 = gelu_exact(v1);
                v2 = gelu_exact(v2); v3 = gelu_exact(v3);
            }
            if (EPI == 2) {
                float2 r0 = *(const float2*)&res[(size_t)row0 * N + col];
                float2 r1 = *(const float2*)&res[(size_t)(row0 + 8) * N + col];
                v0 += r0.x; v1 += r0.y; v2 += r1.x; v3 += r1.y;
            }
            if (OUTHALF) {
                __half* Ch = (__half*)Cout;
                *(uint32_t*)&Ch[(size_t)row0 * N + col]       = pack2(v0, v1);
                *(uint32_t*)&Ch[(size_t)(row0 + 8) * N + col] = pack2(v2, v3);
            } else {
                float* Cf = (float*)Cout;
                *(float2*)&Cf[(size_t)row0 * N + col]       = make_float2(v0, v1);
                *(float2*)&Cf[(size_t)(row0 + 8) * N + col] = make_float2(v2, v3);
            }
        }
    }
}

// ---------------- FP16 flash attention ----------------
// 4 warps; warp w: q-rows [w*16, w*16+16). fp16 qkv in, fp16 ctx out.
// Q/K: [64 rows][64 halves] pitch 72 halves. V transposed: Vt[d][kv].
#define HP 72   // pitch in halves (144 bytes)

__global__ void __launch_bounds__(128) attn_h(const __half* __restrict__ qkv,
                                              __half* __restrict__ ctx) {
    __shared__ __align__(16) __half Qh[64 * HP];
    __shared__ __align__(16) __half Kh[64 * HP];
    __shared__ __align__(16) __half Vt[64 * HP];
    uint32_t qU = (uint32_t)__cvta_generic_to_shared(Qh);
    uint32_t kU = (uint32_t)__cvta_generic_to_shared(Kh);
    uint32_t vU = (uint32_t)__cvta_generic_to_shared(Vt);

    int t = threadIdx.x;
    int warp = t >> 5, lane = t & 31;
    int r4 = lane >> 2, cc = lane & 3;
    int b = blockIdx.z, h = blockIdx.y;
    int s0 = blockIdx.x * 64;
    int wq = warp * 16;

    const __half* qbase = qkv + (size_t)(b * 1024 + s0) * 3072 + h * HEAD_D;
    const __half* kbase = qkv + (size_t)b * 1024 * 3072 + 1024 + h * HEAD_D;
    const __half* vbase = qkv + (size_t)b * 1024 * 3072 + 2048 + h * HEAD_D;

    // load Q (64 x 64 halves)
    #pragma unroll
    for (int p = 0; p < 4; ++p) {
        int j = t + 128 * p;
        int row = j & 63, c8 = j >> 6;
        *(uint4*)&Qh[row * HP + c8 * 8] =
            *(const uint4*)(qbase + (size_t)row * 3072 + c8 * 8);
    }

    // ldsm addresses
    uint32_t aQ = qU + (uint32_t)((wq + (lane & 15)) * 144 + (lane >> 4) * 16);
    uint32_t bK = kU + (uint32_t)(((lane & 7) + ((lane >> 4) << 3)) * 144 +
                                  ((lane >> 3) & 1) * 16);
    uint32_t bV = vU + (uint32_t)(((lane & 7) + ((lane >> 4) << 3)) * 144 +
                                  ((lane >> 3) & 1) * 16);

    float mr_lo = -1e30f, mr_hi = -1e30f, l_lo = 0.f, l_hi = 0.f;
    float oacc[8][4];
    #pragma unroll
    for (int i = 0; i < 8; ++i)
        #pragma unroll
        for (int j = 0; j < 4; ++j) oacc[i][j] = 0.f;
    const float scale = 0.125f;

    for (int j0 = 0; j0 < 1024; j0 += 64) {
        __syncthreads();   // prior tile's K/V reads done
        #pragma unroll
        for (int p = 0; p < 4; ++p) {
            int j = t + 128 * p;
            int row = j & 63, c8 = j >> 6;
            *(uint4*)&Kh[row * HP + c8 * 8] =
                *(const uint4*)(kbase + (size_t)(j0 + row) * 3072 + c8 * 8);
        }
        #pragma unroll
        for (int p = 0; p < 4; ++p) {
            int j = t + 128 * p;
            int kv = j & 63, d8 = j >> 6;
            union { uint4 u; __half hh[8]; } vv;
            vv.u = *(const uint4*)(vbase + (size_t)(j0 + kv) * 3072 + d8 * 8);
            #pragma unroll
            for (int i = 0; i < 8; ++i)
                Vt[(d8 * 8 + i) * HP + kv] = vv.hh[i];
        }
        __syncthreads();

        // ---- S = Q K^T (16 x 64 per warp) ----
        float sacc[8][4];
        #pragma unroll
        for (int i = 0; i < 8; ++i)
            #pragma unroll
            for (int j = 0; j < 4; ++j) sacc[i][j] = 0.f;

        #pragma unroll
        for (int ks = 0; ks < 4; ++ks) {
            uint32_t a0, a1, a2, a3;
            ldsm4(a0, a1, a2, a3, aQ + ks * 32);
            uint32_t bf[8][2];
            #pragma unroll
            for (int nb = 0; nb < 4; ++nb)
                ldsm4(bf[2*nb][0], bf[2*nb][1], bf[2*nb+1][0], bf[2*nb+1][1],
                      bK + nb * (16 * 144) + ks * 32);
            #pragma unroll
            for (int nt = 0; nt < 8; ++nt)
                mma_f16(sacc[nt], a0, a1, a2, a3, bf[nt][0], bf[nt][1]);
        }

        // ---- online softmax (exp results stored back into sacc) ----
        float mlo = -1e30f, mhi = -1e30f;
        #pragma unroll
        for (int nt = 0; nt < 8; ++nt) {
            sacc[nt][0] *= scale; sacc[nt][1] *= scale;
            sacc[nt][2] *= scale; sacc[nt][3] *= scale;
            mlo = fmaxf(mlo, fmaxf(sacc[nt][0], sacc[nt][1]));
            mhi = fmaxf(mhi, fmaxf(sacc[nt][2], sacc[nt][3]));
        }
        mlo = fmaxf(mlo, __shfl_xor_sync(0xffffffffu, mlo, 1));
        mlo = fmaxf(mlo, __shfl_xor_sync(0xffffffffu, mlo, 2));
        mhi = fmaxf(mhi, __shfl_xor_sync(0xffffffffu, mhi, 1));
        mhi = fmaxf(mhi, __shfl_xor_sync(0xffffffffu, mhi, 2));
        float mn_lo = fmaxf(mr_lo, mlo), mn_hi = fmaxf(mr_hi, mhi);
        float al_lo = __expf(mr_lo - mn_lo), al_hi = __expf(mr_hi - mn_hi);

        float ps_lo = 0.f, ps_hi = 0.f;
        #pragma unroll
        for (int nt = 0; nt < 8; ++nt) {
            sacc[nt][0] = __expf(sacc[nt][0] - mn_lo);
            sacc[nt][1] = __expf(sacc[nt][1] - mn_lo);
            sacc[nt][2] = __expf(sacc[nt][2] - mn_hi);
            sacc[nt][3] = __expf(sacc[nt][3] - mn_hi);
            ps_lo += sacc[nt][0] + sacc[nt][1];
            ps_hi += sacc[nt][2] + sacc[nt][3];
        }
        ps_lo += __shfl_xor_sync(0xffffffffu, ps_lo, 1);
        ps_lo += __shfl_xor_sync(0xffffffffu, ps_lo, 2);
        ps_hi += __shfl_xor_sync(0xffffffffu, ps_hi, 1);
        ps_hi += __shfl_xor_sync(0xffffffffu, ps_hi, 2);
        l_lo = l_lo * al_lo + ps_lo;
        l_hi = l_hi * al_hi + ps_hi;
        mr_lo = mn_lo; mr_hi = mn_hi;
        #pragma unroll
        for (int nt = 0; nt < 8; ++nt) {
            oacc[nt][0] *= al_lo; oacc[nt][1] *= al_lo;
            oacc[nt][2] *= al_hi; oacc[nt][3] *= al_hi;
        }

        // ---- O += P V : P acc -> A fragments in registers ----
        #pragma unroll
        for (int kk = 0; kk < 4; ++kk) {
            uint32_t a0 = pack2(sacc[2*kk][0],   sacc[2*kk][1]);
            uint32_t a1 = pack2(sacc[2*kk][2],   sacc[2*kk][3]);
            uint32_t a2 = pack2(sacc[2*kk+1][0], sacc[2*kk+1][1]);
            uint32_t a3 = pack2(sacc[2*kk+1][2], sacc[2*kk+1][3]);
            uint32_t vf[8][2];
            #pragma unroll
            for (int db = 0; db < 4; ++db)
                ldsm4(vf[2*db][0], vf[2*db][1], vf[2*db+1][0], vf[2*db+1][1],
                      bV + db * (16 * 144) + kk * 32);
            #pragma unroll
            for (int nt = 0; nt < 8; ++nt)
                mma_f16(oacc[nt], a0, a1, a2, a3, vf[nt][0], vf[nt][1]);
        }
    }

    float il_lo = 1.f / l_lo, il_hi = 1.f / l_hi;
    int row_lo = b * 1024 + s0 + wq + r4;
    #pragma unroll
    for (int nt = 0; nt < 8; ++nt) {
        int col = h * HEAD_D + nt * 8 + cc * 2;
        *(uint32_t*)&ctx[(size_t)row_lo * D_MODEL + col] =
            pack2(oacc[nt][0] * il_lo, oacc[nt][1] * il_lo);
        *(uint32_t*)&ctx[(size_t)(row_lo + 8) * D_MODEL + col] =
            pack2(oacc[nt][2] * il_hi, oacc[nt][3] * il_hi);
    }
}

// ---------------- launch ----------------
extern "C" void kernel_launch(void* const* d_in, const int* in_sizes, int n_in,
                              void* d_out, int out_size) {
    const float* x      = (const float*)d_in[0];
    const float* qkv_w  = (const float*)d_in[1];
    const float* qkv_b  = (const float*)d_in[2];
    const float* proj_w = (const float*)d_in[3];
    const float* proj_b = (const float*)d_in[4];
    const float* fc1_w  = (const float*)d_in[5];
    const float* fc1_b  = (const float*)d_in[6];
    const float* fc2_w  = (const float*)d_in[7];
    const float* fc2_b  = (const float*)d_in[8];
    const float* ln1_g  = (const float*)d_in[9];
    const float* ln1_b  = (const float*)d_in[10];
    const float* ln2_g  = (const float*)d_in[11];
    const float* ln2_b  = (const float*)d_in[12];
    float* out = (float*)d_out;

    __half *h, *qkv, *ctx, *ff, *wq, *wp, *w1, *w2;
    float *x2;
    cudaGetSymbolAddress((void**)&h,   g_h);
    cudaGetSymbolAddress((void**)&qkv, g_qkv);
    cudaGetSymbolAddress((void**)&ctx, g_ctx);
    cudaGetSymbolAddress((void**)&x2,  g_x2);
    cudaGetSymbolAddress((void**)&ff,  g_ff);
    cudaGetSymbolAddress((void**)&wq,  g_wq);
    cudaGetSymbolAddress((void**)&wp,  g_wp);
    cudaGetSymbolAddress((void**)&w1,  g_w1);
    cudaGetSymbolAddress((void**)&w2,  g_w2);

    int gemm_smem = STAGES * STAGE_BYTES;   // 122880
    cudaFuncSetAttribute(gemm_h<0,1>, cudaFuncAttributeMaxDynamicSharedMemorySize, gemm_smem);
    cudaFuncSetAttribute(gemm_h<2,0>, cudaFuncAttributeMaxDynamicSharedMemorySize, gemm_smem);
    cudaFuncSetAttribute(gemm_h<1,1>, cudaFuncAttributeMaxDynamicSharedMemorySize, gemm_smem);

    conv_w<<<(3*D_MODEL*D_MODEL/4 + 255)/256, 256>>>(qkv_w, wq, 3*D_MODEL*D_MODEL/4);
    conv_w<<<(D_MODEL*D_MODEL/4 + 255)/256, 256>>>(proj_w, wp, D_MODEL*D_MODEL/4);
    conv_w<<<(FF_DIM*D_MODEL/4 + 255)/256, 256>>>(fc1_w, w1, FF_DIM*D_MODEL/4);
    conv_w<<<(D_MODEL*FF_DIM/4 + 255)/256, 256>>>(fc2_w, w2, D_MODEL*FF_DIM/4);

    ln_kernel<<<N_TOK, 256>>>(x, ln1_g, ln1_b, h);
    gemm_h<0,1><<<dim3(3 * D_MODEL / BN, N_TOK / BM2), 512, gemm_smem>>>(
        h, wq, qkv_b, nullptr, qkv, N_TOK, 3 * D_MODEL, D_MODEL);
    attn_h<<<dim3(1024 / 64, N_HEAD, 8), 128>>>(qkv, ctx);
    gemm_h<2,0><<<dim3(D_MODEL / BN, N_TOK / BM2), 512, gemm_smem>>>(
        ctx, wp, proj_b, x, x2, N_TOK, D_MODEL, D_MODEL);
    ln_kernel<<<N_TOK, 256>>>(x2, ln2_g, ln2_b, h);
    gemm_h<1,1><<<dim3(FF_DIM / BN, N_TOK / BM2), 512, gemm_smem>>>(
        h, w1, fc1_b, nullptr, ff, N_TOK, FF_DIM, D_MODEL);
    gemm_h<2,0><<<dim3(D_MODEL / BN, N_TOK / BM2), 512, gemm_smem>>>(
        ff, w2, fc2_b, x2, out, N_TOK, D_MODEL, FF_DIM);
}